// round 3
// baseline (speedup 1.0000x reference)
#include <cuda_runtime.h>
#include <math.h>

#define BATCH 2
#define SEQ   2048
#define EMB   1024
#define NHEAD 16
#define HDIM  64
#define MTOT  (BATCH*SEQ)   // 4096

// Scratch (allocation-free contract: __device__ globals)
__device__ float g_q[BATCH*NHEAD*SEQ*HDIM];   // [b][h][s][d]
__device__ float g_k[BATCH*NHEAD*SEQ*HDIM];
__device__ float g_v[BATCH*NHEAD*SEQ*HDIM];
__device__ float g_ctx[(size_t)MTOT*EMB];     // [b*s][e]

// ---------------------------------------------------------------------------
// SGEMM: C[M,N] = A[M,K] @ W[N,K]^T   (128x128x8 tile, 8x8 micro-tile)
// EPI==0: scatter into g_q/g_k/g_v ([b][h][s][d] layout)
// EPI==1: A = g_ctx, out = C + bias
// ---------------------------------------------------------------------------
template<int EPI>
__global__ __launch_bounds__(256) void sgemm_kernel(
    const float* __restrict__ Ain,
    const float* __restrict__ W,
    const float* __restrict__ bias,
    float* __restrict__ out,
    int M, int N, int K)
{
    const float* A = (EPI == 1) ? (const float*)g_ctx : Ain;

    __shared__ __align__(16) float As[8][128];
    __shared__ __align__(16) float Ws[8][128];

    const int m0  = blockIdx.y * 128;
    const int n0  = blockIdx.x * 128;
    const int tid = threadIdx.x;
    const int tx  = tid & 15;        // 16 col groups
    const int ty  = tid >> 4;        // 16 row groups
    const int lrow = tid >> 1;       // 0..127 (load row)
    const int lcol = (tid & 1) << 2; // 0 or 4 (load col within BK=8)

    const float* aptr = A + (size_t)(m0 + lrow) * K + lcol;
    const float* wptr = W + (size_t)(n0 + lrow) * K + lcol;

    float acc[8][8];
    #pragma unroll
    for (int i = 0; i < 8; i++)
        #pragma unroll
        for (int j = 0; j < 8; j++) acc[i][j] = 0.f;

    for (int k0 = 0; k0 < K; k0 += 8) {
        float4 av = *(const float4*)(aptr + k0);
        float4 wv = *(const float4*)(wptr + k0);
        As[lcol+0][lrow] = av.x; As[lcol+1][lrow] = av.y;
        As[lcol+2][lrow] = av.z; As[lcol+3][lrow] = av.w;
        Ws[lcol+0][lrow] = wv.x; Ws[lcol+1][lrow] = wv.y;
        Ws[lcol+2][lrow] = wv.z; Ws[lcol+3][lrow] = wv.w;
        __syncthreads();

        #pragma unroll
        for (int kk = 0; kk < 8; kk++) {
            float ar[8], wr[8];
            *(float4*)&ar[0] = *(const float4*)&As[kk][ty*8];
            *(float4*)&ar[4] = *(const float4*)&As[kk][ty*8 + 4];
            *(float4*)&wr[0] = *(const float4*)&Ws[kk][tx*8];
            *(float4*)&wr[4] = *(const float4*)&Ws[kk][tx*8 + 4];
            #pragma unroll
            for (int i = 0; i < 8; i++)
                #pragma unroll
                for (int j = 0; j < 8; j++)
                    acc[i][j] = fmaf(ar[i], wr[j], acc[i][j]);
        }
        __syncthreads();
    }

    if (EPI == 0) {
        // n = which*1024 + h*64 + d  -> scatter to [b][h][s][d]
        #pragma unroll
        for (int i = 0; i < 8; i++) {
            int mm = m0 + ty*8 + i;
            int b  = mm >> 11;
            int s  = mm & (SEQ - 1);
            #pragma unroll
            for (int j = 0; j < 8; j++) {
                int nn    = n0 + tx*8 + j;
                int which = nn >> 10;
                int h     = (nn >> 6) & (NHEAD - 1);
                int d     = nn & (HDIM - 1);
                float* dst = (which == 0) ? g_q : ((which == 1) ? g_k : g_v);
                dst[(((b*NHEAD + h)*SEQ) + s)*HDIM + d] = acc[i][j];
            }
        }
    } else {
        #pragma unroll
        for (int i = 0; i < 8; i++) {
            int mm = m0 + ty*8 + i;
            #pragma unroll
            for (int j = 0; j < 8; j++) {
                int nn = n0 + tx*8 + j;
                out[(size_t)mm * N + nn] = acc[i][j] + bias[nn];
            }
        }
    }
}

// ---------------------------------------------------------------------------
// Causal flash attention, fp32, D=64. One block = (b, h, 64 query rows).
// 256 threads: thread tid owns row r = tid>>2, output cols [tg*16, tg*16+16),
// tg = tid&3. Online softmax with shfl reductions over the 4-lane row group.
// Reference scale: scores * sqrt(D) = *8 (folded into Q load).
// ---------------------------------------------------------------------------
__global__ __launch_bounds__(256) void flash_kernel()
{
    __shared__ __align__(16) float Qs[64][65];  // odd pitch: conflict-free row reads
    __shared__ __align__(16) float Ks[64][65];
    __shared__ __align__(16) float Vs[64][68];  // pitch 68: float4-aligned PV reads
    __shared__ __align__(16) float Ps[64][68];

    const int qt = blockIdx.x;
    const int h  = blockIdx.y;
    const int b  = blockIdx.z;
    const int bh = b*NHEAD + h;
    const float* Qg = g_q + (size_t)bh * SEQ * HDIM;
    const float* Kg = g_k + (size_t)bh * SEQ * HDIM;
    const float* Vg = g_v + (size_t)bh * SEQ * HDIM;

    const int tid = threadIdx.x;
    const int r   = tid >> 2;   // query row within tile
    const int tg  = tid & 3;    // column group
    const int q0  = qt * 64;

    // Load Q tile, fold in the *8 scale
    for (int i = tid; i < 64*64; i += 256) {
        int rr = i >> 6, dd = i & 63;
        Qs[rr][dd] = Qg[(q0 + rr)*HDIM + dd] * 8.0f;
    }

    float m = -1e30f, l = 0.f;
    float acc[16];
    #pragma unroll
    for (int j = 0; j < 16; j++) acc[j] = 0.f;

    const int ntiles = qt + 1;  // causal: only tiles with k0 <= q0+63
    for (int kt = 0; kt < ntiles; kt++) {
        const int k0 = kt * 64;
        __syncthreads();  // previous PV done before overwriting K/V
        for (int i = tid; i < 64*64; i += 256) {
            int rr = i >> 6, dd = i & 63;
            Ks[rr][dd] = Kg[(k0 + rr)*HDIM + dd];
            Vs[rr][dd] = Vg[(k0 + rr)*HDIM + dd];
        }
        __syncthreads();

        // scores s[j] = sum_d Q[r][d] * K[tg*16+j][d]
        float p[16];
        #pragma unroll
        for (int j = 0; j < 16; j++) p[j] = 0.f;
        #pragma unroll 8
        for (int d = 0; d < 64; d++) {
            float qv = Qs[r][d];
            #pragma unroll
            for (int j = 0; j < 16; j++)
                p[j] = fmaf(qv, Ks[tg*16 + j][d], p[j]);
        }

        const bool diag = (kt == qt);
        float mloc = -1e30f;
        #pragma unroll
        for (int j = 0; j < 16; j++) {
            if (diag && (k0 + tg*16 + j > q0 + r)) p[j] = -1e30f;
            mloc = fmaxf(mloc, p[j]);
        }
        mloc = fmaxf(mloc, __shfl_xor_sync(0xffffffffu, mloc, 1));
        mloc = fmaxf(mloc, __shfl_xor_sync(0xffffffffu, mloc, 2));
        float mnew = fmaxf(m, mloc);

        float rsum = 0.f;
        #pragma unroll
        for (int j = 0; j < 16; j++) {
            float e = __expf(p[j] - mnew);
            p[j] = e;
            rsum += e;
        }
        rsum += __shfl_xor_sync(0xffffffffu, rsum, 1);
        rsum += __shfl_xor_sync(0xffffffffu, rsum, 2);

        float alpha = __expf(m - mnew);
        m = mnew;
        l = l * alpha + rsum;

        #pragma unroll
        for (int j = 0; j < 16; j++) {
            Ps[r][tg*16 + j] = p[j];
            acc[j] *= alpha;
        }
        __syncthreads();  // Ps visible to all row-group threads

        // acc[j] += sum_k P[r][k] * V[k][tg*16+j]
        #pragma unroll 4
        for (int kk = 0; kk < 64; kk++) {
            float pw = Ps[r][kk];
            const float4* vrow = (const float4*)&Vs[kk][tg*16];
            #pragma unroll
            for (int jj = 0; jj < 4; jj++) {
                float4 v = vrow[jj];
                acc[jj*4+0] = fmaf(pw, v.x, acc[jj*4+0]);
                acc[jj*4+1] = fmaf(pw, v.y, acc[jj*4+1]);
                acc[jj*4+2] = fmaf(pw, v.z, acc[jj*4+2]);
                acc[jj*4+3] = fmaf(pw, v.w, acc[jj*4+3]);
            }
        }
    }

    // ctx[b][s][h*64 + d] = acc / l
    float inv = 1.0f / l;
    const int srow = q0 + r;
    float* outp = g_ctx + ((size_t)(b*SEQ + srow)) * EMB + h*HDIM + tg*16;
    #pragma unroll
    for (int j = 0; j < 16; j++) outp[j] = acc[j] * inv;
}

// ---------------------------------------------------------------------------
// Inputs (metadata order): x [2,2048,1024] f32, w_qkv [3072,1024] f32,
// w_proj [1024,1024] f32, b_proj [1024] f32. Output: [2,2048,1024] f32.
// ---------------------------------------------------------------------------
extern "C" void kernel_launch(void* const* d_in, const int* in_sizes, int n_in,
                              void* d_out, int out_size)
{
    (void)in_sizes; (void)n_in; (void)out_size;
    const float* x      = (const float*)d_in[0];
    const float* w_qkv  = (const float*)d_in[1];
    const float* w_proj = (const float*)d_in[2];
    const float* b_proj = (const float*)d_in[3];
    float* out = (float*)d_out;

    // 1) QKV GEMM: [4096,1024] @ [3072,1024]^T -> scatter to g_q/g_k/g_v
    dim3 g1((3*EMB)/128, MTOT/128);
    sgemm_kernel<0><<<g1, 256>>>(x, w_qkv, nullptr, nullptr, MTOT, 3*EMB, EMB);

    // 2) Causal flash attention -> g_ctx
    dim3 g2(SEQ/64, NHEAD, BATCH);
    flash_kernel<<<g2, 256>>>();

    // 3) Proj GEMM + bias: g_ctx @ w_proj^T + b_proj -> out
    dim3 g3(EMB/128, MTOT/128);
    sgemm_kernel<1><<<g3, 256>>>(nullptr, w_proj, b_proj, out, MTOT, EMB, EMB);
}

// round 4
// speedup vs baseline: 2.1539x; 2.1539x over previous
#include <cuda_runtime.h>
#include <math.h>

#define BATCH 2
#define SEQ   2048
#define EMB   1024
#define NHEAD 16
#define HDIM  64
#define MTOT  (BATCH*SEQ)   // 4096

// Scratch (allocation-free contract: __device__ globals)
__device__ float g_q[BATCH*NHEAD*SEQ*HDIM];   // [b][h][s][d]
__device__ float g_k[BATCH*NHEAD*SEQ*HDIM];
__device__ float g_v[BATCH*NHEAD*SEQ*HDIM];
__device__ float g_ctx[(size_t)MTOT*EMB];     // [b*s][e]

// ---------------------------------------------------------------------------
// SGEMM: C[M,N] = A[M,K] @ W[N,K]^T   (128x128x8 tile, 8x8 micro-tile)
// EPI==0: scatter into g_q/g_k/g_v ([b][h][s][d] layout)
// EPI==1: A = g_ctx, out = C + bias
// (unchanged from R2 — measured at ~36 TF/s, the fp32 FFMA issue ceiling)
// ---------------------------------------------------------------------------
template<int EPI>
__global__ __launch_bounds__(256) void sgemm_kernel(
    const float* __restrict__ Ain,
    const float* __restrict__ W,
    const float* __restrict__ bias,
    float* __restrict__ out,
    int M, int N, int K)
{
    const float* A = (EPI == 1) ? (const float*)g_ctx : Ain;

    __shared__ __align__(16) float As[8][128];
    __shared__ __align__(16) float Ws[8][128];

    const int m0  = blockIdx.y * 128;
    const int n0  = blockIdx.x * 128;
    const int tid = threadIdx.x;
    const int tx  = tid & 15;        // 16 col groups
    const int ty  = tid >> 4;        // 16 row groups
    const int lrow = tid >> 1;       // 0..127 (load row)
    const int lcol = (tid & 1) << 2; // 0 or 4 (load col within BK=8)

    const float* aptr = A + (size_t)(m0 + lrow) * K + lcol;
    const float* wptr = W + (size_t)(n0 + lrow) * K + lcol;

    float acc[8][8];
    #pragma unroll
    for (int i = 0; i < 8; i++)
        #pragma unroll
        for (int j = 0; j < 8; j++) acc[i][j] = 0.f;

    for (int k0 = 0; k0 < K; k0 += 8) {
        float4 av = *(const float4*)(aptr + k0);
        float4 wv = *(const float4*)(wptr + k0);
        As[lcol+0][lrow] = av.x; As[lcol+1][lrow] = av.y;
        As[lcol+2][lrow] = av.z; As[lcol+3][lrow] = av.w;
        Ws[lcol+0][lrow] = wv.x; Ws[lcol+1][lrow] = wv.y;
        Ws[lcol+2][lrow] = wv.z; Ws[lcol+3][lrow] = wv.w;
        __syncthreads();

        #pragma unroll
        for (int kk = 0; kk < 8; kk++) {
            float ar[8], wr[8];
            *(float4*)&ar[0] = *(const float4*)&As[kk][ty*8];
            *(float4*)&ar[4] = *(const float4*)&As[kk][ty*8 + 4];
            *(float4*)&wr[0] = *(const float4*)&Ws[kk][tx*8];
            *(float4*)&wr[4] = *(const float4*)&Ws[kk][tx*8 + 4];
            #pragma unroll
            for (int i = 0; i < 8; i++)
                #pragma unroll
                for (int j = 0; j < 8; j++)
                    acc[i][j] = fmaf(ar[i], wr[j], acc[i][j]);
        }
        __syncthreads();
    }

    if (EPI == 0) {
        #pragma unroll
        for (int i = 0; i < 8; i++) {
            int mm = m0 + ty*8 + i;
            int b  = mm >> 11;
            int s  = mm & (SEQ - 1);
            #pragma unroll
            for (int j = 0; j < 8; j++) {
                int nn    = n0 + tx*8 + j;
                int which = nn >> 10;
                int h     = (nn >> 6) & (NHEAD - 1);
                int d     = nn & (HDIM - 1);
                float* dst = (which == 0) ? g_q : ((which == 1) ? g_k : g_v);
                dst[(((b*NHEAD + h)*SEQ) + s)*HDIM + d] = acc[i][j];
            }
        }
    } else {
        #pragma unroll
        for (int i = 0; i < 8; i++) {
            int mm = m0 + ty*8 + i;
            #pragma unroll
            for (int j = 0; j < 8; j++) {
                int nn = n0 + tx*8 + j;
                out[(size_t)mm * N + nn] = acc[i][j] + bias[nn];
            }
        }
    }
}

// ---------------------------------------------------------------------------
// Causal flash attention, fp32, D=64, REGISTER-BLOCKED.
// One block = (b, h, 64 query rows). 256 threads in a 16x16 grid:
//   ty = tid>>4 owns query rows r0 = ty*4 .. +3
//   tx = tid&15 owns cols      c0 = tx*4 .. +3
// Each thread computes a 4x4 score / ctx micro-tile => 16 FMA per 8 LDS.
// Smem pitches: Qs/Ks/Ps = 65 (scalar reads: broadcast or <=2-way conflict),
// Vs/Ps-store = 68 (16B-aligned rows for float4).
// Per-row softmax state reduced across the 16 tx lanes via shfl_xor (1,2,4,8
// stay within the warp since lane = (ty&1)*16 + tx).
// Reference scale: scores * sqrt(D) = *8 (folded into Q load).
// ---------------------------------------------------------------------------
__global__ __launch_bounds__(256) void flash_kernel()
{
    __shared__ __align__(16) float Qs[64][65];
    __shared__ __align__(16) float Ks[64][65];
    __shared__ __align__(16) float Vs[64][68];  // float4 row reads
    __shared__ __align__(16) float Ps[64][68];  // float4 writes, broadcast reads

    const int qt = blockIdx.x;
    const int h  = blockIdx.y;
    const int b  = blockIdx.z;
    const int bh = b*NHEAD + h;
    const float* Qg = g_q + (size_t)bh * SEQ * HDIM;
    const float* Kg = g_k + (size_t)bh * SEQ * HDIM;
    const float* Vg = g_v + (size_t)bh * SEQ * HDIM;

    const int tid = threadIdx.x;
    const int ty  = tid >> 4;
    const int tx  = tid & 15;
    const int r0  = ty * 4;
    const int c0  = tx * 4;
    const int q0  = qt * 64;

    // Load Q tile (fold in *8 scale). 64 rows x 16 float4-chunks.
    for (int i = tid; i < 64*16; i += 256) {
        int rr = i >> 4, ff = (i & 15) << 2;
        float4 v = *(const float4*)(Qg + (size_t)(q0 + rr)*HDIM + ff);
        Qs[rr][ff+0] = v.x*8.f; Qs[rr][ff+1] = v.y*8.f;
        Qs[rr][ff+2] = v.z*8.f; Qs[rr][ff+3] = v.w*8.f;
    }

    float m[4], l[4], acc[4][4];
    #pragma unroll
    for (int i = 0; i < 4; i++) {
        m[i] = -1e30f; l[i] = 0.f;
        #pragma unroll
        for (int j = 0; j < 4; j++) acc[i][j] = 0.f;
    }

    for (int kt = 0; kt <= qt; kt++) {
        __syncthreads();  // prior PV reads of Vs/Ps done; Q visible (1st iter)
        for (int i = tid; i < 64*16; i += 256) {
            int rr = i >> 4, ff = (i & 15) << 2;
            float4 kv = *(const float4*)(Kg + (size_t)(kt*64 + rr)*HDIM + ff);
            float4 vv = *(const float4*)(Vg + (size_t)(kt*64 + rr)*HDIM + ff);
            Ks[rr][ff+0] = kv.x; Ks[rr][ff+1] = kv.y;
            Ks[rr][ff+2] = kv.z; Ks[rr][ff+3] = kv.w;
            *(float4*)&Vs[rr][ff] = vv;
        }
        __syncthreads();

        // ---- scores: 4x4 micro-tile, contract over d ----
        float s[4][4];
        #pragma unroll
        for (int i = 0; i < 4; i++)
            #pragma unroll
            for (int j = 0; j < 4; j++) s[i][j] = 0.f;

        #pragma unroll 8
        for (int d = 0; d < 64; d++) {
            float qf[4], kf[4];
            #pragma unroll
            for (int i = 0; i < 4; i++) qf[i] = Qs[r0+i][d];  // ty-broadcast
            #pragma unroll
            for (int j = 0; j < 4; j++) kf[j] = Ks[c0+j][d];  // ~2-way
            #pragma unroll
            for (int i = 0; i < 4; i++)
                #pragma unroll
                for (int j = 0; j < 4; j++)
                    s[i][j] = fmaf(qf[i], kf[j], s[i][j]);
        }

        // ---- causal mask (diagonal tile only; k0 == q0 there) ----
        if (kt == qt) {
            #pragma unroll
            for (int i = 0; i < 4; i++)
                #pragma unroll
                for (int j = 0; j < 4; j++)
                    if (c0 + j > r0 + i) s[i][j] = -1e30f;
        }

        // ---- online softmax, per-row over the 16 tx lanes ----
        float mnew[4], rsum[4];
        #pragma unroll
        for (int i = 0; i < 4; i++) {
            float mloc = fmaxf(fmaxf(s[i][0], s[i][1]), fmaxf(s[i][2], s[i][3]));
            mloc = fmaxf(mloc, __shfl_xor_sync(0xffffffffu, mloc, 1));
            mloc = fmaxf(mloc, __shfl_xor_sync(0xffffffffu, mloc, 2));
            mloc = fmaxf(mloc, __shfl_xor_sync(0xffffffffu, mloc, 4));
            mloc = fmaxf(mloc, __shfl_xor_sync(0xffffffffu, mloc, 8));
            mnew[i] = fmaxf(m[i], mloc);
        }
        #pragma unroll
        for (int i = 0; i < 4; i++) {
            float rs = 0.f;
            #pragma unroll
            for (int j = 0; j < 4; j++) {
                float e = __expf(s[i][j] - mnew[i]);
                s[i][j] = e;
                rs += e;
            }
            rs += __shfl_xor_sync(0xffffffffu, rs, 1);
            rs += __shfl_xor_sync(0xffffffffu, rs, 2);
            rs += __shfl_xor_sync(0xffffffffu, rs, 4);
            rs += __shfl_xor_sync(0xffffffffu, rs, 8);
            rsum[i] = rs;
        }
        #pragma unroll
        for (int i = 0; i < 4; i++) {
            float alpha = __expf(m[i] - mnew[i]);
            m[i] = mnew[i];
            l[i] = l[i] * alpha + rsum[i];
            #pragma unroll
            for (int j = 0; j < 4; j++) acc[i][j] *= alpha;
            *(float4*)&Ps[r0+i][c0] = make_float4(s[i][0], s[i][1], s[i][2], s[i][3]);
        }
        __syncthreads();  // Ps visible across tx

        // ---- PV: acc[i][j] += sum_k P[r0+i][k] * V[k][c0+j] ----
        #pragma unroll 8
        for (int k = 0; k < 64; k++) {
            float pf[4];
            #pragma unroll
            for (int i = 0; i < 4; i++) pf[i] = Ps[r0+i][k];   // ty-broadcast
            float4 v = *(const float4*)&Vs[k][c0];             // float4 row
            #pragma unroll
            for (int i = 0; i < 4; i++) {
                acc[i][0] = fmaf(pf[i], v.x, acc[i][0]);
                acc[i][1] = fmaf(pf[i], v.y, acc[i][1]);
                acc[i][2] = fmaf(pf[i], v.z, acc[i][2]);
                acc[i][3] = fmaf(pf[i], v.w, acc[i][3]);
            }
        }
    }

    // ctx[b][s][h*64 + c0..c0+3] = acc / l, float4 stores
    #pragma unroll
    for (int i = 0; i < 4; i++) {
        float inv = 1.0f / l[i];
        float* outp = g_ctx + ((size_t)(b*SEQ + q0 + r0 + i)) * EMB + h*HDIM + c0;
        *(float4*)outp = make_float4(acc[i][0]*inv, acc[i][1]*inv,
                                     acc[i][2]*inv, acc[i][3]*inv);
    }
}

// ---------------------------------------------------------------------------
// Inputs (metadata order): x [2,2048,1024] f32, w_qkv [3072,1024] f32,
// w_proj [1024,1024] f32, b_proj [1024] f32. Output: [2,2048,1024] f32.
// ---------------------------------------------------------------------------
extern "C" void kernel_launch(void* const* d_in, const int* in_sizes, int n_in,
                              void* d_out, int out_size)
{
    (void)in_sizes; (void)n_in; (void)out_size;
    const float* x      = (const float*)d_in[0];
    const float* w_qkv  = (const float*)d_in[1];
    const float* w_proj = (const float*)d_in[2];
    const float* b_proj = (const float*)d_in[3];
    float* out = (float*)d_out;

    // 1) QKV GEMM: [4096,1024] @ [3072,1024]^T -> scatter to g_q/g_k/g_v
    dim3 g1((3*EMB)/128, MTOT/128);
    sgemm_kernel<0><<<g1, 256>>>(x, w_qkv, nullptr, nullptr, MTOT, 3*EMB, EMB);

    // 2) Causal flash attention -> g_ctx
    dim3 g2(SEQ/64, NHEAD, BATCH);
    flash_kernel<<<g2, 256>>>();

    // 3) Proj GEMM + bias: g_ctx @ w_proj^T + b_proj -> out
    dim3 g3(EMB/128, MTOT/128);
    sgemm_kernel<1><<<g3, 256>>>(nullptr, w_proj, b_proj, out, MTOT, EMB, EMB);
}